// round 1
// baseline (speedup 1.0000x reference)
#include <cuda_runtime.h>
#include <math.h>

#define N_   64
#define C_   512
#define P_   1024
#define KA   65     // clusters incl. ghost
#define KC   64     // kept clusters
#define EPSF 1e-12f

// ---------------- scratch (device globals: allocation-free) ----------------
__device__ float g_inv[N_ * P_];          // 256 KB  per-pixel 1/||x||
__device__ float g_a[N_ * KC * P_];       // 16.8 MB softmax weights (kept k only)
__device__ float g_asum[N_ * KC];         // sum_p a[k,p]
__device__ float g_agg[N_ * KC * C_];     // 8.4 MB  sum_p a[k,p]*xn[c,p]
__device__ float g_nsq[N_];               // per-sample total sumsq after row-norm

// ---------------- kernel 1: per-pixel inverse L2 norm ----------------
// grid (64, 4) x 256 threads; thread = one pixel, coalesced over p.
__global__ void __launch_bounds__(256) k_norm(const float* __restrict__ x) {
    int n = blockIdx.x;
    int p = blockIdx.y * 256 + threadIdx.x;
    const float* xp = x + (size_t)n * C_ * P_ + p;
    float s = 0.f;
#pragma unroll 8
    for (int c = 0; c < C_; c++) {
        float v = xp[(size_t)c * P_];
        s = fmaf(v, v, s);
    }
    g_inv[n * P_ + p] = 1.f / fmaxf(sqrtf(s), EPSF);
    if (blockIdx.y == 0 && threadIdx.x == 0) g_nsq[n] = 0.f;  // reset accumulator
}

// ---------------- kernel 2: logits + softmax -> a ----------------
// grid (64, 8) x 128 threads; thread = one pixel, 65 accumulators in regs,
// conv_w staged per-64-channel chunk in smem, read as float4.
__global__ void __launch_bounds__(128) k_logits(const float* __restrict__ x,
                                                const float* __restrict__ w,
                                                const float* __restrict__ b) {
    __shared__ float ws[64 * 68];   // [cc][k], padded to 68
    __shared__ float bs[KA];
    int n = blockIdx.x;
    int p = blockIdx.y * 128 + threadIdx.x;
    if (threadIdx.x < KA) bs[threadIdx.x] = b[threadIdx.x];

    float4 acc[16];
    float  acc64 = 0.f;
#pragma unroll
    for (int j = 0; j < 16; j++) acc[j] = make_float4(0.f, 0.f, 0.f, 0.f);

    const float* xp = x + (size_t)n * C_ * P_ + p;

    for (int c0 = 0; c0 < C_; c0 += 64) {
        __syncthreads();
        for (int i = threadIdx.x; i < KA * 64; i += 128) {
            int k = i >> 6, cc = i & 63;
            ws[cc * 68 + k] = w[k * C_ + c0 + cc];
        }
        __syncthreads();
#pragma unroll 4
        for (int cc = 0; cc < 64; cc++) {
            float xv = xp[(size_t)(c0 + cc) * P_];
            const float4* wr = reinterpret_cast<const float4*>(ws + cc * 68);
#pragma unroll
            for (int j = 0; j < 16; j++) {
                float4 wv = wr[j];
                acc[j].x = fmaf(wv.x, xv, acc[j].x);
                acc[j].y = fmaf(wv.y, xv, acc[j].y);
                acc[j].z = fmaf(wv.z, xv, acc[j].z);
                acc[j].w = fmaf(wv.w, xv, acc[j].w);
            }
            acc64 = fmaf(ws[cc * 68 + 64], xv, acc64);
        }
    }

    float inv = g_inv[n * P_ + p];
    float l[KA];
#pragma unroll
    for (int j = 0; j < 16; j++) {
        l[4 * j + 0] = fmaf(acc[j].x, inv, bs[4 * j + 0]);
        l[4 * j + 1] = fmaf(acc[j].y, inv, bs[4 * j + 1]);
        l[4 * j + 2] = fmaf(acc[j].z, inv, bs[4 * j + 2]);
        l[4 * j + 3] = fmaf(acc[j].w, inv, bs[4 * j + 3]);
    }
    l[64] = fmaf(acc64, inv, bs[64]);

    float m = l[0];
#pragma unroll
    for (int k = 1; k < KA; k++) m = fmaxf(m, l[k]);
    float s = 0.f;
#pragma unroll
    for (int k = 0; k < KA; k++) {
        float e = __expf(l[k] - m);
        l[k] = e;
        s += e;
    }
    float rs = 1.f / s;

    float* ao = g_a + (size_t)n * KC * P_ + p;
#pragma unroll
    for (int k = 0; k < KC; k++) ao[(size_t)k * P_] = l[k] * rs;
}

// ---------------- kernel 3: asum[n][k] = sum_p a ----------------
// grid (64, 64) x 256 threads
__global__ void __launch_bounds__(256) k_asum() {
    int n = blockIdx.x, k = blockIdx.y;
    int tid = threadIdx.x;
    const float* ap = g_a + ((size_t)n * KC + k) * P_;
    float s = 0.f;
    for (int p = tid; p < P_; p += 256) s += ap[p];
#pragma unroll
    for (int o = 16; o; o >>= 1) s += __shfl_xor_sync(0xFFFFFFFFu, s, o);
    __shared__ float red[8];
    if ((tid & 31) == 0) red[tid >> 5] = s;
    __syncthreads();
    if (tid == 0) {
        float t = 0.f;
#pragma unroll
        for (int i = 0; i < 8; i++) t += red[i];
        g_asum[n * KC + k] = t;
    }
}

// ---------------- kernel 4: aggregation GEMM ----------------
// agg[n][k][c] = sum_p a[k,p] * x[c,p] * inv[p]
// grid (64, 4) x 256 threads; output tile 64k x 128c; thread = 4k x 8c microtile.
__global__ void __launch_bounds__(256) k_agg(const float* __restrict__ x) {
    __shared__ float as_[32 * 68];    // [p][k] pad 68
    __shared__ float xs[32 * 132];    // [p][c] pad 132, inv folded in
    int n = blockIdx.x;
    int cbase = blockIdx.y * 128;
    int tid = threadIdx.x;
    int tx = tid & 15;        // c group: 8 c's
    int ty = tid >> 4;        // k group: 4 k's

    float acc[4][8];
#pragma unroll
    for (int i = 0; i < 4; i++)
#pragma unroll
        for (int j = 0; j < 8; j++) acc[i][j] = 0.f;

    for (int p0 = 0; p0 < P_; p0 += 32) {
        __syncthreads();
        for (int i = tid; i < KC * 32; i += 256) {
            int k = i >> 5, pp = i & 31;
            as_[pp * 68 + k] = g_a[((size_t)n * KC + k) * P_ + p0 + pp];
        }
        for (int i = tid; i < 128 * 32; i += 256) {
            int c = i >> 5, pp = i & 31;
            xs[pp * 132 + c] =
                x[((size_t)n * C_ + cbase + c) * P_ + p0 + pp] * g_inv[n * P_ + p0 + pp];
        }
        __syncthreads();
#pragma unroll 4
        for (int pp = 0; pp < 32; pp++) {
            float4 av  = *reinterpret_cast<const float4*>(as_ + pp * 68 + ty * 4);
            float4 xv0 = *reinterpret_cast<const float4*>(xs + pp * 132 + tx * 8);
            float4 xv1 = *reinterpret_cast<const float4*>(xs + pp * 132 + tx * 8 + 4);
            float av_[4] = {av.x, av.y, av.z, av.w};
            float xv_[8] = {xv0.x, xv0.y, xv0.z, xv0.w, xv1.x, xv1.y, xv1.z, xv1.w};
#pragma unroll
            for (int i = 0; i < 4; i++)
#pragma unroll
                for (int j = 0; j < 8; j++) acc[i][j] = fmaf(av_[i], xv_[j], acc[i][j]);
        }
    }
#pragma unroll
    for (int i = 0; i < 4; i++) {
        int k = ty * 4 + i;
        float* dst = g_agg + ((size_t)n * KC + k) * C_ + cbase + tx * 8;
#pragma unroll
        for (int j = 0; j < 8; j++) dst[j] = acc[i][j];
    }
}

// ---------------- kernel 5: centroid subtract + per-row L2 norm ----------------
// grid (64, 64) x 128 threads; thread handles 4 c's
__global__ void __launch_bounds__(128) k_rownorm(const float* __restrict__ cent,
                                                 float* __restrict__ out) {
    int n = blockIdx.x, k = blockIdx.y;
    int tid = threadIdx.x;
    float as = g_asum[n * KC + k];
    float v[4];
    float s = 0.f;
#pragma unroll
    for (int j = 0; j < 4; j++) {
        int c = tid + j * 128;
        float val = g_agg[((size_t)n * KC + k) * C_ + c] - as * cent[k * C_ + c];
        v[j] = val;
        s = fmaf(val, val, s);
    }
#pragma unroll
    for (int o = 16; o; o >>= 1) s += __shfl_xor_sync(0xFFFFFFFFu, s, o);
    __shared__ float red[4];
    __shared__ float tot;
    if ((tid & 31) == 0) red[tid >> 5] = s;
    __syncthreads();
    if (tid == 0) tot = red[0] + red[1] + red[2] + red[3];
    __syncthreads();
    float total = tot;
    float invn = 1.f / fmaxf(sqrtf(total), EPSF);
#pragma unroll
    for (int j = 0; j < 4; j++) {
        int c = tid + j * 128;
        out[(size_t)n * KC * C_ + (size_t)k * C_ + c] = v[j] * invn;
    }
    if (tid == 0) atomicAdd(&g_nsq[n], total * invn * invn);
}

// ---------------- kernel 6: global L2 normalize ----------------
// grid (64, 32) x 256 threads, float4 per thread: 32*256*4 = 32768 per sample
__global__ void __launch_bounds__(256) k_final(float* __restrict__ out) {
    int n = blockIdx.x;
    float scale = 1.f / fmaxf(sqrtf(g_nsq[n]), EPSF);
    size_t idx = (size_t)n * (KC * C_) + ((size_t)blockIdx.y * 256 + threadIdx.x) * 4;
    float4* o = reinterpret_cast<float4*>(out + idx);
    float4 v = *o;
    v.x *= scale; v.y *= scale; v.z *= scale; v.w *= scale;
    *o = v;
}

// ---------------- launch ----------------
extern "C" void kernel_launch(void* const* d_in, const int* in_sizes, int n_in,
                              void* d_out, int out_size) {
    const float* x    = (const float*)d_in[0];
    const float* w    = (const float*)d_in[1];
    const float* b    = (const float*)d_in[2];
    const float* cent = (const float*)d_in[3];
    float* out = (float*)d_out;

    k_norm<<<dim3(N_, 4), 256>>>(x);
    k_logits<<<dim3(N_, 8), 128>>>(x, w, b);
    k_asum<<<dim3(N_, KC), 256>>>();
    k_agg<<<dim3(N_, 4), 256>>>(x);
    k_rownorm<<<dim3(N_, KC), 128>>>(cent, out);
    k_final<<<dim3(N_, 32), 256>>>(out);
}

// round 2
// speedup vs baseline: 1.2675x; 1.2675x over previous
#include <cuda_runtime.h>
#include <math.h>
#include <stdint.h>

#define N_   64
#define C_   512
#define P_   1024
#define KA   65     // clusters incl. ghost
#define KC   64     // kept clusters
#define EPSF 1e-12f
#define QSPLIT 4    // p-splits for k_agg

// ---------------- scratch (device globals: allocation-free) ----------------
__device__ float g_inv[N_ * P_];                    // per-pixel 1/||x||
__device__ float g_a[N_ * KC * P_];                 // 16.8 MB softmax weights
__device__ float g_asum[N_ * KC];                   // sum_p a[k,p]
__device__ float g_aggp[QSPLIT * N_ * KC * C_];     // 33.5 MB partial aggregation
__device__ float g_nsq[N_];                         // per-sample sumsq accumulator

#define FMA2(d, a, b) asm("fma.rn.f32x2 %0, %1, %2, %0;" : "+l"(d) : "l"(a), "l"(b))
#define PACK2(d, lo, hi) asm("mov.b64 %0, {%1, %2};" : "=l"(d) : "f"(lo), "f"(hi))
#define UNPACK2(lo, hi, s) asm("mov.b64 {%0, %1}, %2;" : "=f"(lo), "=f"(hi) : "l"(s))
#define LDSV2U64(a, b, addr) \
    asm volatile("ld.shared.v2.b64 {%0, %1}, [%2];" : "=l"(a), "=l"(b) : "r"(addr))

// ---------------- kernel 1: logits + softmax -> a  (norm fused in) ----------------
// grid (64, 8) x 128 threads; thread = one pixel; 65 accumulators (32 packed + 1),
// conv_w staged per-64-channel chunk in smem, packed f32x2 FMA over k.
__global__ void __launch_bounds__(128) k_logits(const float* __restrict__ x,
                                                const float* __restrict__ w,
                                                const float* __restrict__ b) {
    __shared__ float ws[64 * 68];   // [cc][k], row pad 68 floats (272B, 16B-aligned)
    __shared__ float bs[KA];
    int n = blockIdx.x;
    int p = blockIdx.y * 128 + threadIdx.x;
    if (threadIdx.x < KA) bs[threadIdx.x] = b[threadIdx.x];

    unsigned long long acc2[32];
#pragma unroll
    for (int j = 0; j < 32; j++) acc2[j] = 0ULL;   // (0.f,0.f)
    float acc64 = 0.f, sumsq = 0.f;

    const float* xp = x + (size_t)n * C_ * P_ + p;
    uint32_t wsb = (uint32_t)__cvta_generic_to_shared(ws);

    for (int c0 = 0; c0 < C_; c0 += 64) {
        __syncthreads();
        for (int i = threadIdx.x; i < KA * 64; i += 128) {
            int k = i >> 6, cc = i & 63;
            ws[cc * 68 + k] = w[k * C_ + c0 + cc];
        }
        __syncthreads();
#pragma unroll 4
        for (int cc = 0; cc < 64; cc++) {
            float xv = xp[(size_t)(c0 + cc) * P_];
            sumsq = fmaf(xv, xv, sumsq);
            unsigned long long xv2;
            PACK2(xv2, xv, xv);
            uint32_t rb = wsb + cc * 272;
#pragma unroll
            for (int j = 0; j < 16; j++) {
                unsigned long long w0, w1;
                LDSV2U64(w0, w1, rb + j * 16);
                FMA2(acc2[2 * j], xv2, w0);
                FMA2(acc2[2 * j + 1], xv2, w1);
            }
            acc64 = fmaf(ws[cc * 68 + 64], xv, acc64);
        }
    }

    float inv = 1.f / fmaxf(sqrtf(sumsq), EPSF);
    g_inv[n * P_ + p] = inv;

    float l[KA];
#pragma unroll
    for (int j = 0; j < 32; j++) {
        float lo, hi;
        UNPACK2(lo, hi, acc2[j]);
        l[2 * j]     = fmaf(lo, inv, bs[2 * j]);
        l[2 * j + 1] = fmaf(hi, inv, bs[2 * j + 1]);
    }
    l[64] = fmaf(acc64, inv, bs[64]);

    float m = l[0];
#pragma unroll
    for (int k = 1; k < KA; k++) m = fmaxf(m, l[k]);
    float s = 0.f;
#pragma unroll
    for (int k = 0; k < KA; k++) {
        float e = __expf(l[k] - m);
        l[k] = e;
        s += e;
    }
    float rs = 1.f / s;

    float* ao = g_a + (size_t)n * KC * P_ + p;
#pragma unroll
    for (int k = 0; k < KC; k++) ao[(size_t)k * P_] = l[k] * rs;
}

// ---------------- kernel 2: asum[n][k] = sum_p a (+ reset g_nsq) ----------------
__global__ void __launch_bounds__(256) k_asum() {
    int n = blockIdx.x, k = blockIdx.y;
    int tid = threadIdx.x;
    if (k == 0 && tid == 0) g_nsq[n] = 0.f;
    const float* ap = g_a + ((size_t)n * KC + k) * P_;
    float s = 0.f;
    for (int p = tid; p < P_; p += 256) s += ap[p];
#pragma unroll
    for (int o = 16; o; o >>= 1) s += __shfl_xor_sync(0xFFFFFFFFu, s, o);
    __shared__ float red[8];
    if ((tid & 31) == 0) red[tid >> 5] = s;
    __syncthreads();
    if (tid == 0) {
        float t = 0.f;
#pragma unroll
        for (int i = 0; i < 8; i++) t += red[i];
        g_asum[n * KC + k] = t;
    }
}

// ---------------- kernel 3: aggregation GEMM (p-split x4, f32x2 packed) ----------------
// aggp[q][n][k][c] = sum_{p in quarter q} a[k,p] * x[c,p] * inv[p]
// grid (64, 4, 4) x 256 threads; tile 64k x 128c x 256p; thread = 4k x 8c.
__global__ void __launch_bounds__(256) k_agg(const float* __restrict__ x) {
    __shared__ float as_[32 * 68];    // [pp][k]  row 272B
    __shared__ float xs[32 * 132];    // [pp][c]  row 528B, inv folded in
    int n = blockIdx.x;
    int cbase = blockIdx.y * 128;
    int q = blockIdx.z;
    int tid = threadIdx.x;
    int tx = tid & 15;        // c group: 8 c's
    int ty = tid >> 4;        // k group: 4 k's

    unsigned long long acc2[4][4];    // [k][c-pair]
#pragma unroll
    for (int i = 0; i < 4; i++)
#pragma unroll
        for (int j = 0; j < 4; j++) acc2[i][j] = 0ULL;

    uint32_t asb = (uint32_t)__cvta_generic_to_shared(as_);
    uint32_t xsb = (uint32_t)__cvta_generic_to_shared(xs);
    int p_end = q * 256 + 256;

    for (int p0 = q * 256; p0 < p_end; p0 += 32) {
        __syncthreads();
        for (int i = tid; i < KC * 32; i += 256) {
            int k = i >> 5, pp = i & 31;
            as_[pp * 68 + k] = g_a[((size_t)n * KC + k) * P_ + p0 + pp];
        }
        for (int i = tid; i < 128 * 32; i += 256) {
            int c = i >> 5, pp = i & 31;
            xs[pp * 132 + c] =
                x[((size_t)n * C_ + cbase + c) * P_ + p0 + pp] * g_inv[n * P_ + p0 + pp];
        }
        __syncthreads();
#pragma unroll 4
        for (int pp = 0; pp < 32; pp++) {
            float4 av = *reinterpret_cast<const float4*>(as_ + pp * 68 + ty * 4);
            unsigned long long a0, a1, a2, a3;
            PACK2(a0, av.x, av.x);
            PACK2(a1, av.y, av.y);
            PACK2(a2, av.z, av.z);
            PACK2(a3, av.w, av.w);
            unsigned long long x0, x1, x2, x3;
            uint32_t xr = xsb + pp * 528 + tx * 32;
            LDSV2U64(x0, x1, xr);
            LDSV2U64(x2, x3, xr + 16);
            FMA2(acc2[0][0], a0, x0); FMA2(acc2[0][1], a0, x1);
            FMA2(acc2[0][2], a0, x2); FMA2(acc2[0][3], a0, x3);
            FMA2(acc2[1][0], a1, x0); FMA2(acc2[1][1], a1, x1);
            FMA2(acc2[1][2], a1, x2); FMA2(acc2[1][3], a1, x3);
            FMA2(acc2[2][0], a2, x0); FMA2(acc2[2][1], a2, x1);
            FMA2(acc2[2][2], a2, x2); FMA2(acc2[2][3], a2, x3);
            FMA2(acc2[3][0], a3, x0); FMA2(acc2[3][1], a3, x1);
            FMA2(acc2[3][2], a3, x2); FMA2(acc2[3][3], a3, x3);
        }
    }
#pragma unroll
    for (int i = 0; i < 4; i++) {
        int k = ty * 4 + i;
        float v[8];
#pragma unroll
        for (int j = 0; j < 4; j++) UNPACK2(v[2 * j], v[2 * j + 1], acc2[i][j]);
        float* dst = g_aggp + (((size_t)q * N_ + n) * KC + k) * C_ + cbase + tx * 8;
        *reinterpret_cast<float4*>(dst)     = make_float4(v[0], v[1], v[2], v[3]);
        *reinterpret_cast<float4*>(dst + 4) = make_float4(v[4], v[5], v[6], v[7]);
    }
}

// ---------------- kernel 4: partial-sum + centroid subtract + per-row L2 ----------------
// grid (64, 64) x 128 threads; thread handles 4 c's
__global__ void __launch_bounds__(128) k_rownorm(const float* __restrict__ cent,
                                                 float* __restrict__ out) {
    int n = blockIdx.x, k = blockIdx.y;
    int tid = threadIdx.x;
    float as = g_asum[n * KC + k];
    float v[4];
    float s = 0.f;
    size_t base = ((size_t)n * KC + k) * C_;
    const size_t qstride = (size_t)N_ * KC * C_;
#pragma unroll
    for (int j = 0; j < 4; j++) {
        int c = tid + j * 128;
        float val = g_aggp[base + c] + g_aggp[qstride + base + c] +
                    g_aggp[2 * qstride + base + c] + g_aggp[3 * qstride + base + c] -
                    as * cent[k * C_ + c];
        v[j] = val;
        s = fmaf(val, val, s);
    }
#pragma unroll
    for (int o = 16; o; o >>= 1) s += __shfl_xor_sync(0xFFFFFFFFu, s, o);
    __shared__ float red[4];
    __shared__ float tot;
    if ((tid & 31) == 0) red[tid >> 5] = s;
    __syncthreads();
    if (tid == 0) tot = red[0] + red[1] + red[2] + red[3];
    __syncthreads();
    float total = tot;
    float invn = 1.f / fmaxf(sqrtf(total), EPSF);
#pragma unroll
    for (int j = 0; j < 4; j++) {
        int c = tid + j * 128;
        out[(size_t)n * KC * C_ + (size_t)k * C_ + c] = v[j] * invn;
    }
    if (tid == 0) atomicAdd(&g_nsq[n], total * invn * invn);
}

// ---------------- kernel 5: global L2 normalize ----------------
__global__ void __launch_bounds__(256) k_final(float* __restrict__ out) {
    int n = blockIdx.x;
    float scale = 1.f / fmaxf(sqrtf(g_nsq[n]), EPSF);
    size_t idx = (size_t)n * (KC * C_) + ((size_t)blockIdx.y * 256 + threadIdx.x) * 4;
    float4* o = reinterpret_cast<float4*>(out + idx);
    float4 v = *o;
    v.x *= scale; v.y *= scale; v.z *= scale; v.w *= scale;
    *o = v;
}

// ---------------- launch ----------------
extern "C" void kernel_launch(void* const* d_in, const int* in_sizes, int n_in,
                              void* d_out, int out_size) {
    const float* x    = (const float*)d_in[0];
    const float* w    = (const float*)d_in[1];
    const float* b    = (const float*)d_in[2];
    const float* cent = (const float*)d_in[3];
    float* out = (float*)d_out;

    k_logits<<<dim3(N_, 8), 128>>>(x, w, b);
    k_asum<<<dim3(N_, KC), 256>>>();
    k_agg<<<dim3(N_, 4, QSPLIT), 256>>>(x);
    k_rownorm<<<dim3(N_, KC), 128>>>(cent, out);
    k_final<<<dim3(N_, 32), 256>>>(out);
}